// round 16
// baseline (speedup 1.0000x reference)
#include <cuda_runtime.h>
#include <cuda_fp16.h>
#include <cstdint>
#include <math.h>

#define NTOK  500
#define NTOKP 512
#define DM    2048
#define KWIN  10
#define NREL  21
#define NQKV  6144
#define SPL_S 8

// ---------------- scratch (device globals; no allocation allowed) ----------
__device__ __align__(16) __half g_X16 [NTOK * DM];
__device__ __align__(16) __half g_W16 [DM * NQKV];     // [k][Wq|Wk|Wv]
__device__ __align__(16) __half g_Wo16[DM * DM];
__device__ __align__(16) __half g_QKV16[NTOK * NQKV];  // [tok][Q|K|V]
__device__ __align__(16) __half g_A16 [NTOK * NTOKP];  // attention, zero-padded cols
__device__ __align__(16) __half g_T16 [NTOK * DM];
__device__ __align__(16) float g_P [2 * NTOK * NQKV];  // split-K partials
__device__ float g_S [NTOK * NTOK];
__device__ float g_QR[NTOK * NREL];

// ---------------- PTX helpers ----------------------------------------------
__device__ __forceinline__ uint32_t smem_to_u32(const void* p) {
    uint32_t a;
    asm("{ .reg .u64 t; cvta.to.shared.u64 t, %1; cvt.u32.u64 %0, t; }" : "=r"(a) : "l"(p));
    return a;
}
__device__ __forceinline__ void cp16(uint32_t sa, const void* g, bool v) {
    asm volatile("cp.async.ca.shared.global [%0], [%1], 16, %2;"
                 :: "r"(sa), "l"(g), "r"(v ? 16u : 0u) : "memory");
}
__device__ __forceinline__ void ldsm4(uint32_t& r0, uint32_t& r1, uint32_t& r2, uint32_t& r3,
                                      uint32_t addr) {
    asm volatile("ldmatrix.sync.aligned.m8n8.x4.shared.b16 {%0,%1,%2,%3}, [%4];"
                 : "=r"(r0), "=r"(r1), "=r"(r2), "=r"(r3) : "r"(addr));
}
__device__ __forceinline__ void ldsm4t(uint32_t& r0, uint32_t& r1, uint32_t& r2, uint32_t& r3,
                                       uint32_t addr) {
    asm volatile("ldmatrix.sync.aligned.m8n8.x4.trans.shared.b16 {%0,%1,%2,%3}, [%4];"
                 : "=r"(r0), "=r"(r1), "=r"(r2), "=r"(r3) : "r"(addr));
}
__device__ __forceinline__ void mma16816(float* c, const uint32_t* a, uint32_t b0, uint32_t b1) {
    asm volatile("mma.sync.aligned.m16n8k16.row.col.f32.f16.f16.f32 "
                 "{%0,%1,%2,%3}, {%4,%5,%6,%7}, {%8,%9}, {%0,%1,%2,%3};"
                 : "+f"(c[0]), "+f"(c[1]), "+f"(c[2]), "+f"(c[3])
                 : "r"(a[0]), "r"(a[1]), "r"(a[2]), "r"(a[3]), "r"(b0), "r"(b1));
}

// ---------------------------------------------------------------------------
// Split-K fp16 GEMM (R8 core).  chunk z = zBase + blockIdx.z
//   FUSE=false: P[z] = alpha * A @ op(B)   (fp32 partial)
//   FUSE=true : C16o  = fp16(alpha * A @ op(B) + Padd)   (final fused chunk)
//   MODEB=0: B [N][K] row-major => A @ B^T   MODEB=1: B [K][N] row-major => A @ B
// CTA tile (MI*32) x 128, BK=64, 8 warps, 3-stage cp.async, 1 barrier/iter.
// ---------------------------------------------------------------------------
#define BK 64
#define SA  72
#define SB1 136
#define NSTAGE 3

template<int MODEB, int MI, bool FUSE>
__global__ __launch_bounds__(256, 2) void hgemm(
    const __half* __restrict__ A, const __half* __restrict__ B,
    float* __restrict__ P,
    int M, int N, int kLen, int KB,
    int ldA, int ldB, int ldC, size_t chunkStride, float alpha, int zBase,
    __half* __restrict__ C16o, const float* __restrict__ Padd)
{
    constexpr int BM = MI * 32;
    constexpr int A_BYT = BM * SA * 2;
    constexpr int B_BYT = MODEB ? (64 * SB1 * 2) : (128 * SA * 2);
    constexpr int STG = A_BYT + B_BYT;
    constexpr int ACH = BM * 8 / 256;
    constexpr int BCH = 4;

    extern __shared__ char smem[];
    const uint32_t sb = smem_to_u32(smem);

    const int tid = threadIdx.x;
    const int lane = tid & 31, w = tid >> 5;
    const int wm = w & 1, wn = w >> 1;
    const int bm = blockIdx.y * BM, bn = blockIdx.x * 128;
    const int z = zBase + blockIdx.z;
    const int kOff = z * kLen;
    const int nIter = kLen / BK;
    float* Cp = P + (size_t)z * chunkStride;

    const __half* pA[ACH];  bool vA[ACH];  uint32_t oA[ACH];
#pragma unroll
    for (int i = 0; i < ACH; i++) {
        int ch = tid + 256 * i;
        int r = ch >> 3, cb = ch & 7;
        pA[i] = A + (size_t)(bm + r) * ldA + kOff + cb * 8;
        vA[i] = (bm + r) < M;
        oA[i] = (r * SA + cb * 8) * 2;
    }
    const __half* pB[BCH];  bool vB[BCH];  int rB[BCH];  uint32_t oB[BCH];
#pragma unroll
    for (int i = 0; i < BCH; i++) {
        int ch = tid + 256 * i;
        if (MODEB) {
            int r = ch >> 4, cb = ch & 15;
            pB[i] = B + (size_t)(kOff + r) * ldB + bn + cb * 8;
            rB[i] = kOff + r;
            vB[i] = true;
            oB[i] = (r * SB1 + cb * 8) * 2;
        } else {
            int r = ch >> 3, cb = ch & 7;
            pB[i] = B + (size_t)(bn + r) * ldB + kOff + cb * 8;
            vB[i] = (bn + r) < N;
            rB[i] = 0;
            oB[i] = (r * SA + cb * 8) * 2;
        }
    }
    const size_t bStep = MODEB ? (size_t)BK * ldB : (size_t)BK;

    auto load = [&](int buf) {
        const uint32_t aS = sb + (uint32_t)buf * STG;
        const uint32_t bS = aS + A_BYT;
#pragma unroll
        for (int i = 0; i < ACH; i++) { cp16(aS + oA[i], pA[i], vA[i]); pA[i] += BK; }
#pragma unroll
        for (int i = 0; i < BCH; i++) {
            bool ok = MODEB ? (rB[i] < KB) : vB[i];
            cp16(bS + oB[i], pB[i], ok);
            pB[i] += bStep;
            if (MODEB) rB[i] += BK;
        }
        asm volatile("cp.async.commit_group;" ::: "memory");
    };

    float acc[MI][4][4];
#pragma unroll
    for (int i = 0; i < MI; i++)
#pragma unroll
        for (int j = 0; j < 4; j++)
#pragma unroll
            for (int t = 0; t < 4; t++) acc[i][j][t] = 0.f;

    load(0);
    load(1);

    const int arow  = lane & 15;
    const int acol  = (lane >> 4) * 8;
    const int b0row = (lane & 7) + ((lane >> 4) & 1) * 8;
    const int b0col = ((lane >> 3) & 1) * 8;
    const int b1row = (lane & 7) + ((lane >> 3) & 1) * 8;
    const int b1col = ((lane >> 4) & 1) * 8;

    for (int it = 0; it < nIter; ++it) {
        asm volatile("cp.async.wait_group 1;" ::: "memory");
        __syncthreads();

        const uint32_t aS = sb + (uint32_t)(it % NSTAGE) * STG;
        const uint32_t bS = aS + A_BYT;

#pragma unroll
        for (int kk = 0; kk < 4; kk++) {
            uint32_t a[MI][4];
#pragma unroll
            for (int mi = 0; mi < MI; mi++) {
                uint32_t addr = aS + (uint32_t)((((wm * MI + mi) * 16 + arow) * SA) + kk * 16 + acol) * 2;
                ldsm4(a[mi][0], a[mi][1], a[mi][2], a[mi][3], addr);
            }
            uint32_t b[2][4];
#pragma unroll
            for (int nb = 0; nb < 2; nb++) {
                if (MODEB) {
                    uint32_t addr = bS + (uint32_t)(((kk * 16 + b1row) * SB1) + wn * 32 + nb * 16 + b1col) * 2;
                    ldsm4t(b[nb][0], b[nb][1], b[nb][2], b[nb][3], addr);
                } else {
                    uint32_t addr = bS + (uint32_t)(((wn * 32 + nb * 16 + b0row) * SA) + kk * 16 + b0col) * 2;
                    ldsm4(b[nb][0], b[nb][1], b[nb][2], b[nb][3], addr);
                }
            }
#pragma unroll
            for (int mi = 0; mi < MI; mi++)
#pragma unroll
                for (int nj = 0; nj < 4; nj++)
                    mma16816(acc[mi][nj], a[mi],
                             b[nj >> 1][2 * (nj & 1)], b[nj >> 1][2 * (nj & 1) + 1]);

            if (kk == 0) {
                if (it + 2 < nIter) load((it + 2) % NSTAGE);
                else asm volatile("cp.async.commit_group;" ::: "memory");
            }
        }
    }

    // ---- epilogue (FUSE variant compiled only into its own instantiation) --
#pragma unroll
    for (int mi = 0; mi < MI; mi++) {
        const int r0 = bm + (wm * MI + mi) * 16 + (lane >> 2);
#pragma unroll
        for (int nj = 0; nj < 4; nj++) {
            const int c0 = bn + wn * 32 + nj * 8 + 2 * (lane & 3);
            const float* ac = acc[mi][nj];
            if (FUSE) {
                if (r0 < M && c0 < N) {
                    float2 ad = *(const float2*)(Padd + (size_t)r0 * ldC + c0);
                    *(__half2*)(C16o + (size_t)r0 * ldC + c0) =
                        __floats2half2_rn(ac[0] * alpha + ad.x, ac[1] * alpha + ad.y);
                }
                if (r0 + 8 < M && c0 < N) {
                    float2 ad = *(const float2*)(Padd + (size_t)(r0 + 8) * ldC + c0);
                    *(__half2*)(C16o + (size_t)(r0 + 8) * ldC + c0) =
                        __floats2half2_rn(ac[2] * alpha + ad.x, ac[3] * alpha + ad.y);
                }
            } else {
                if (r0 < M && c0 < N)
                    *(float2*)(Cp + (size_t)r0 * ldC + c0) =
                        make_float2(ac[0] * alpha, ac[1] * alpha);
                if (r0 + 8 < M && c0 < N)
                    *(float2*)(Cp + (size_t)(r0 + 8) * ldC + c0) =
                        make_float2(ac[2] * alpha, ac[3] * alpha);
            }
        }
    }
}

// ---------------------------------------------------------------------------
__global__ void reduce2h(const float* __restrict__ P, size_t CH,
                         __half* __restrict__ out, int n4) {
    int i = blockIdx.x * blockDim.x + threadIdx.x;
    if (i < n4) {
        float4 a = *(const float4*)(P + 4 * (size_t)i);
        float4 b = *(const float4*)(P + CH + 4 * (size_t)i);
        __half2* o = (__half2*)(out + 4 * (size_t)i);
        o[0] = __floats2half2_rn(a.x + b.x, a.y + b.y);
        o[1] = __floats2half2_rn(a.z + b.z, a.w + b.w);
    }
}
__global__ void reduce2f(const float* __restrict__ P, size_t CH,
                         float* __restrict__ out, int n4) {
    int i = blockIdx.x * blockDim.x + threadIdx.x;
    if (i < n4) {
        float4 a = *(const float4*)(P + 4 * (size_t)i);
        float4 b = *(const float4*)(P + CH + 4 * (size_t)i);
        *(float4*)(out + 4 * (size_t)i) =
            make_float4(a.x + b.x, a.y + b.y, a.z + b.z, a.w + b.w);
    }
}

// ---------------------------------------------------------------------------
__global__ void cvt1(const float4* __restrict__ s, __half2* __restrict__ d, int n4) {
    int i = blockIdx.x * blockDim.x + threadIdx.x;
    if (i < n4) {
        float4 v = s[i];
        d[2 * i]     = __floats2half2_rn(v.x, v.y);
        d[2 * i + 1] = __floats2half2_rn(v.z, v.w);
    }
}
__global__ void cvt_fuse3(const float4* __restrict__ q, const float4* __restrict__ k,
                          const float4* __restrict__ v, __half* __restrict__ d, int n4) {
    int i = blockIdx.x * blockDim.x + threadIdx.x;
    if (i < n4) {
        int p = i * 4;
        int row = p >> 11, col = p & 2047;
        float4 a;
        __half2* dq = (__half2*)(d + (size_t)row * NQKV + col);
        a = q[i]; dq[0] = __floats2half2_rn(a.x, a.y); dq[1] = __floats2half2_rn(a.z, a.w);
        __half2* dk = (__half2*)(d + (size_t)row * NQKV + 2048 + col);
        a = k[i]; dk[0] = __floats2half2_rn(a.x, a.y); dk[1] = __floats2half2_rn(a.z, a.w);
        __half2* dv = (__half2*)(d + (size_t)row * NQKV + 4096 + col);
        a = v[i]; dv[0] = __floats2half2_rn(a.x, a.y); dv[1] = __floats2half2_rn(a.z, a.w);
    }
}

// ---------------------------------------------------------------------------
#define QR_BLOCKS 25
#define QR_ROWS   20
#define QR_THREADS (NREL * 32)
#define QR_SMEM ((NREL * DM + DM) * 4)

__global__ __launch_bounds__(QR_THREADS, 1) void qr_kernel(
    const __half* __restrict__ Q, int ldQ, const float* __restrict__ wk,
    float* __restrict__ QR, float scale)
{
    extern __shared__ float qsm[];
    float* wks = qsm;
    float* qv  = qsm + NREL * DM;
    const int tid = threadIdx.x, warp = tid / 32, lane = tid & 31;

    for (int t = tid; t < NREL * DM; t += QR_THREADS) wks[t] = wk[t];
    __syncthreads();

    for (int ii = 0; ii < QR_ROWS; ii++) {
        const int i = blockIdx.x * QR_ROWS + ii;
        for (int t = tid; t < DM; t += QR_THREADS)
            qv[t] = __half2float(Q[(size_t)i * ldQ + t]);
        __syncthreads();
        if (warp < NREL) {
            float s = 0.f;
            const float* wp = wks + warp * DM;
#pragma unroll 4
            for (int k = lane; k < DM; k += 32) s += qv[k] * wp[k];
#pragma unroll
            for (int o = 16; o > 0; o >>= 1) s += __shfl_xor_sync(0xffffffffu, s, o);
            if (lane == 0) QR[i * NREL + warp] = s * scale;
        }
        __syncthreads();
    }
}

// ---------------------------------------------------------------------------
__global__ __launch_bounds__(512) void softmax_kernel(
    const float* __restrict__ SP, float* __restrict__ S,
    const float* __restrict__ QR, const int* __restrict__ mask,
    float* __restrict__ Aout, __half* __restrict__ A16, int n)
{
    const int i = blockIdx.x;
    __shared__ float red[512];
    const size_t CH = (size_t)NTOK * NTOK;
    float* row = S + (size_t)i * n;
    const int* mrow = mask + (size_t)i * n;
    float* arow = Aout + (size_t)i * n;
    __half* hrow = A16 + (size_t)i * NTOKP;

    float m = -INFINITY;
    for (int j = threadIdx.x; j < n; j += blockDim.x) {
        float v = 0.f;
        const size_t off = (size_t)i * n + j;
#pragma unroll
        for (int z = 0; z < SPL_S; z++) v += SP[z * CH + off];
        int d = j - i;
        d = min(max(d, -KWIN), KWIN);
        v += QR[i * NREL + d + KWIN];
        if (mrow[j] == 0) v = -1e9f;
        row[j] = v;
        m = fmaxf(m, v);
    }
    red[threadIdx.x] = m;
    __syncthreads();
    for (int s = 256; s > 0; s >>= 1) {
        if (threadIdx.x < s) red[threadIdx.x] = fmaxf(red[threadIdx.x], red[threadIdx.x + s]);
        __syncthreads();
    }
    m = red[0];
    __syncthreads();

    float sum = 0.f;
    for (int j = threadIdx.x; j < n; j += blockDim.x) {
        float e = expf(row[j] - m);
        row[j] = e;
        sum += e;
    }
    red[threadIdx.x] = sum;
    __syncthreads();
    for (int s = 256; s > 0; s >>= 1) {
        if (threadIdx.x < s) red[threadIdx.x] += red[threadIdx.x + s];
        __syncthreads();
    }
    const float inv = 1.0f / red[0];
    __syncthreads();

    for (int j = threadIdx.x; j < n; j += blockDim.x) {
        float a = row[j] * inv;
        arow[j] = a;
        hrow[j] = __float2half_rn(a);
    }
    for (int j = n + threadIdx.x; j < NTOKP; j += blockDim.x) hrow[j] = __float2half_rn(0.f);
}

// ---------------------------------------------------------------------------
extern "C" void kernel_launch(void* const* d_in, const int* in_sizes, int n_in,
                              void* d_out, int out_size)
{
    const float* X    = (const float*)d_in[0];
    const int*   mask = (const int*)  d_in[1];
    const float* Wq   = (const float*)d_in[2];
    const float* Wk   = (const float*)d_in[3];
    const float* Wv   = (const float*)d_in[4];
    const float* Wo   = (const float*)d_in[5];
    const float* wk   = (const float*)d_in[6];

    float* Y    = (float*)d_out;                 // [500, 2048]
    float* Aout = Y + (size_t)NTOK * DM;         // [500, 500]

    __half *X16, *W16, *Wo16, *QKV16, *A16, *T16;
    float *P, *S, *QR;
    cudaGetSymbolAddress((void**)&X16,   g_X16);
    cudaGetSymbolAddress((void**)&W16,   g_W16);
    cudaGetSymbolAddress((void**)&Wo16,  g_Wo16);
    cudaGetSymbolAddress((void**)&QKV16, g_QKV16);
    cudaGetSymbolAddress((void**)&A16,   g_A16);
    cudaGetSymbolAddress((void**)&T16,   g_T16);
    cudaGetSymbolAddress((void**)&P,     g_P);
    cudaGetSymbolAddress((void**)&S,     g_S);
    cudaGetSymbolAddress((void**)&QR,    g_QR);

    const int SM_1_4 = NSTAGE * (128 * SA * 2 + 64 * SB1 * 2);   // 107520
    const int SM_0_2 = NSTAGE * (64 * SA * 2 + 128 * SA * 2);    // 82944
    const int SM_1_2 = NSTAGE * (64 * SA * 2 + 64 * SB1 * 2);    // 79872
    cudaFuncSetAttribute((const void*)hgemm<1,4,false>, cudaFuncAttributeMaxDynamicSharedMemorySize, SM_1_4);
    cudaFuncSetAttribute((const void*)hgemm<1,4,true>,  cudaFuncAttributeMaxDynamicSharedMemorySize, SM_1_4);
    cudaFuncSetAttribute((const void*)hgemm<0,2,false>, cudaFuncAttributeMaxDynamicSharedMemorySize, SM_0_2);
    cudaFuncSetAttribute((const void*)hgemm<1,2,false>, cudaFuncAttributeMaxDynamicSharedMemorySize, SM_1_2);
    cudaFuncSetAttribute((const void*)qr_kernel,        cudaFuncAttributeMaxDynamicSharedMemorySize, QR_SMEM);

    static cudaStream_t s2 = nullptr;
    static cudaEvent_t e0 = nullptr, eW0 = nullptr, eW1 = nullptr,
                       eQ = nullptr, eR = nullptr, eWo = nullptr;
    if (!s2) {
        cudaStreamCreateWithFlags(&s2, cudaStreamNonBlocking);
        cudaEventCreateWithFlags(&e0,  cudaEventDisableTiming);
        cudaEventCreateWithFlags(&eW0, cudaEventDisableTiming);
        cudaEventCreateWithFlags(&eW1, cudaEventDisableTiming);
        cudaEventCreateWithFlags(&eQ,  cudaEventDisableTiming);
        cudaEventCreateWithFlags(&eR,  cudaEventDisableTiming);
        cudaEventCreateWithFlags(&eWo, cudaEventDisableTiming);
    }

    const float scale = 1.0f / sqrtf((float)DM);
    const size_t CH_QKV = (size_t)NTOK * NQKV;
    const size_t CH_S   = (size_t)NTOK * NTOK;
    const size_t CH_TD  = (size_t)NTOK * DM;
    const int HALF4 = DM * DM / 8;
    const int HOFF4 = 1024 * DM / 4;

    // fork side stream
    cudaEventRecord(e0, 0);
    cudaStreamWaitEvent(s2, e0, 0);

    // main: X cvt, then W slab 0 cvt (k rows 0..1023)
    cvt1<<<(NTOK * DM / 4 + 255) / 256, 256>>>((const float4*)X, (__half2*)X16, NTOK * DM / 4);
    cvt_fuse3<<<(HALF4 + 255) / 256, 256>>>(
        (const float4*)Wq, (const float4*)Wk, (const float4*)Wv, W16, HALF4);
    cudaEventRecord(eW0, 0);

    // side: W slab 1 cvt (hidden under z0), then Wo cvt
    cudaStreamWaitEvent(s2, eW0, 0);
    cvt_fuse3<<<(HALF4 + 255) / 256, 256, 0, s2>>>(
        (const float4*)Wq + HOFF4, (const float4*)Wk + HOFF4, (const float4*)Wv + HOFF4,
        W16 + (size_t)1024 * NQKV, HALF4);
    cudaEventRecord(eW1, s2);
    cvt1<<<(DM * DM / 4 + 255) / 256, 256, 0, s2>>>(
        (const float4*)Wo, (__half2*)Wo16, DM * DM / 4);
    cudaEventRecord(eWo, s2);

    // main: QKV chunk z=0 -> fp32 partial (chunk 0 of P)
    hgemm<1,4,false><<<dim3(NQKV / 128, 4, 1), 256, SM_1_4>>>(
        X16, W16, P, NTOK, NQKV, 1024, DM, DM, NQKV, NQKV, CH_QKV, 1.0f, 0,
        nullptr, nullptr);

    // main: QKV chunk z=1 FUSED (add chunk-0 partial, emit fp16 QKV16)
    cudaStreamWaitEvent(0, eW1, 0);
    hgemm<1,4,true><<<dim3(NQKV / 128, 4, 1), 256, SM_1_4>>>(
        X16, W16, P, NTOK, NQKV, 1024, DM, DM, NQKV, NQKV, CH_QKV, 1.0f, 1,
        QKV16, P);
    cudaEventRecord(eQ, 0);

    // side: QR concurrent with S GEMM
    cudaStreamWaitEvent(s2, eQ, 0);
    qr_kernel<<<QR_BLOCKS, QR_THREADS, QR_SMEM, s2>>>(QKV16, NQKV, wk, QR, scale);
    cudaEventRecord(eR, s2);

    // main: S partials = scale * Q @ K^T, split-K 8
    hgemm<0,2,false><<<dim3(4, 8, SPL_S), 256, SM_0_2>>>(
        QKV16, QKV16 + DM, P, NTOK, NTOK, 256, DM, NQKV, NQKV, NTOK, CH_S, scale, 0,
        nullptr, nullptr);

    // main: fused 8-way reduce + bias + mask + softmax (needs qr)
    cudaStreamWaitEvent(0, eR, 0);
    softmax_kernel<<<NTOK, 512>>>(P, S, QR, mask, Aout, A16, NTOK);

    // main: T = A @ V, split-K 2 (K padded to 512, V rows >=500 masked)
    hgemm<1,2,false><<<dim3(DM / 128, 8, 2), 256, SM_1_2>>>(
        A16, QKV16 + 2 * DM, P, NTOK, DM, 256, NTOK, NTOKP, NQKV, DM, CH_TD, 1.0f, 0,
        nullptr, nullptr);
    reduce2h<<<((int)CH_TD / 4 + 255) / 256, 256>>>(P, CH_TD, T16, (int)CH_TD / 4);

    // main: Y = T @ Wo, split-K 2 (fp32 out; needs Wo16)
    cudaStreamWaitEvent(0, eWo, 0);
    hgemm<1,2,false><<<dim3(DM / 128, 8, 2), 256, SM_1_2>>>(
        T16, Wo16, P, NTOK, DM, 1024, DM, DM, DM, DM, CH_TD, 1.0f, 0,
        nullptr, nullptr);
    reduce2f<<<((int)CH_TD / 4 + 255) / 256, 256>>>(P, CH_TD, Y, (int)CH_TD / 4);
}

// round 17
// speedup vs baseline: 1.0640x; 1.0640x over previous
#include <cuda_runtime.h>
#include <cuda_fp16.h>
#include <cstdint>
#include <math.h>

#define NTOK  500
#define NTOKP 512
#define DM    2048
#define KWIN  10
#define NREL  21
#define NQKV  6144
#define SPL_S 8

// ---------------- scratch (device globals; no allocation allowed) ----------
__device__ __align__(16) __half g_X16 [NTOK * DM];
__device__ __align__(16) __half g_W16 [DM * NQKV];     // [k][Wq|Wk|Wv]
__device__ __align__(16) __half g_Wo16[DM * DM];
__device__ __align__(16) __half g_QKV16[NTOK * NQKV];  // [tok][Q|K|V]
__device__ __align__(16) __half g_A16 [NTOK * NTOKP];  // attention, zero-padded cols
__device__ __align__(16) __half g_T16 [NTOK * DM];
__device__ __align__(16) float g_P [2 * NTOK * NQKV];  // split-K partials
__device__ float g_S [NTOK * NTOK];
__device__ float g_QR[NTOK * NREL];

// ---------------- PTX helpers ----------------------------------------------
__device__ __forceinline__ uint32_t smem_to_u32(const void* p) {
    uint32_t a;
    asm("{ .reg .u64 t; cvta.to.shared.u64 t, %1; cvt.u32.u64 %0, t; }" : "=r"(a) : "l"(p));
    return a;
}
__device__ __forceinline__ void cp16(uint32_t sa, const void* g, bool v) {
    asm volatile("cp.async.ca.shared.global [%0], [%1], 16, %2;"
                 :: "r"(sa), "l"(g), "r"(v ? 16u : 0u) : "memory");
}
__device__ __forceinline__ void ldsm4(uint32_t& r0, uint32_t& r1, uint32_t& r2, uint32_t& r3,
                                      uint32_t addr) {
    asm volatile("ldmatrix.sync.aligned.m8n8.x4.shared.b16 {%0,%1,%2,%3}, [%4];"
                 : "=r"(r0), "=r"(r1), "=r"(r2), "=r"(r3) : "r"(addr));
}
__device__ __forceinline__ void ldsm4t(uint32_t& r0, uint32_t& r1, uint32_t& r2, uint32_t& r3,
                                       uint32_t addr) {
    asm volatile("ldmatrix.sync.aligned.m8n8.x4.trans.shared.b16 {%0,%1,%2,%3}, [%4];"
                 : "=r"(r0), "=r"(r1), "=r"(r2), "=r"(r3) : "r"(addr));
}
__device__ __forceinline__ void mma16816(float* c, const uint32_t* a, uint32_t b0, uint32_t b1) {
    asm volatile("mma.sync.aligned.m16n8k16.row.col.f32.f16.f16.f32 "
                 "{%0,%1,%2,%3}, {%4,%5,%6,%7}, {%8,%9}, {%0,%1,%2,%3};"
                 : "+f"(c[0]), "+f"(c[1]), "+f"(c[2]), "+f"(c[3])
                 : "r"(a[0]), "r"(a[1]), "r"(a[2]), "r"(a[3]), "r"(b0), "r"(b1));
}

// ---------------------------------------------------------------------------
// Split-K fp16 GEMM (R8 core).  P[z] = alpha * A[M, kOff:+kLen] @ op(B)
//   z = zBase + blockIdx.z
//   MODEB=0: B [N][K] row-major => A @ B^T   MODEB=1: B [K][N] row-major => A @ B
// CTA tile (MI*32) x 128, BK=64, 8 warps, 3-stage cp.async,
// 1 barrier/iter, loop-invariant load addressing.
// ---------------------------------------------------------------------------
#define BK 64
#define SA  72
#define SB1 136
#define NSTAGE 3

template<int MODEB, int MI>
__global__ __launch_bounds__(256, 2) void hgemm(
    const __half* __restrict__ A, const __half* __restrict__ B,
    float* __restrict__ P,
    int M, int N, int kLen, int KB,
    int ldA, int ldB, int ldC, size_t chunkStride, float alpha, int zBase)
{
    constexpr int BM = MI * 32;
    constexpr int A_BYT = BM * SA * 2;
    constexpr int B_BYT = MODEB ? (64 * SB1 * 2) : (128 * SA * 2);
    constexpr int STG = A_BYT + B_BYT;
    constexpr int ACH = BM * 8 / 256;
    constexpr int BCH = 4;

    extern __shared__ char smem[];
    const uint32_t sb = smem_to_u32(smem);

    const int tid = threadIdx.x;
    const int lane = tid & 31, w = tid >> 5;
    const int wm = w & 1, wn = w >> 1;
    const int bm = blockIdx.y * BM, bn = blockIdx.x * 128;
    const int z = zBase + blockIdx.z;
    const int kOff = z * kLen;
    const int nIter = kLen / BK;
    float* Cp = P + (size_t)z * chunkStride;

    const __half* pA[ACH];  bool vA[ACH];  uint32_t oA[ACH];
#pragma unroll
    for (int i = 0; i < ACH; i++) {
        int ch = tid + 256 * i;
        int r = ch >> 3, cb = ch & 7;
        pA[i] = A + (size_t)(bm + r) * ldA + kOff + cb * 8;
        vA[i] = (bm + r) < M;
        oA[i] = (r * SA + cb * 8) * 2;
    }
    const __half* pB[BCH];  bool vB[BCH];  int rB[BCH];  uint32_t oB[BCH];
#pragma unroll
    for (int i = 0; i < BCH; i++) {
        int ch = tid + 256 * i;
        if (MODEB) {
            int r = ch >> 4, cb = ch & 15;
            pB[i] = B + (size_t)(kOff + r) * ldB + bn + cb * 8;
            rB[i] = kOff + r;
            vB[i] = true;
            oB[i] = (r * SB1 + cb * 8) * 2;
        } else {
            int r = ch >> 3, cb = ch & 7;
            pB[i] = B + (size_t)(bn + r) * ldB + kOff + cb * 8;
            vB[i] = (bn + r) < N;
            rB[i] = 0;
            oB[i] = (r * SA + cb * 8) * 2;
        }
    }
    const size_t bStep = MODEB ? (size_t)BK * ldB : (size_t)BK;

    auto load = [&](int buf) {
        const uint32_t aS = sb + (uint32_t)buf * STG;
        const uint32_t bS = aS + A_BYT;
#pragma unroll
        for (int i = 0; i < ACH; i++) { cp16(aS + oA[i], pA[i], vA[i]); pA[i] += BK; }
#pragma unroll
        for (int i = 0; i < BCH; i++) {
            bool ok = MODEB ? (rB[i] < KB) : vB[i];
            cp16(bS + oB[i], pB[i], ok);
            pB[i] += bStep;
            if (MODEB) rB[i] += BK;
        }
        asm volatile("cp.async.commit_group;" ::: "memory");
    };

    float acc[MI][4][4];
#pragma unroll
    for (int i = 0; i < MI; i++)
#pragma unroll
        for (int j = 0; j < 4; j++)
#pragma unroll
            for (int t = 0; t < 4; t++) acc[i][j][t] = 0.f;

    load(0);
    load(1);

    const int arow  = lane & 15;
    const int acol  = (lane >> 4) * 8;
    const int b0row = (lane & 7) + ((lane >> 4) & 1) * 8;
    const int b0col = ((lane >> 3) & 1) * 8;
    const int b1row = (lane & 7) + ((lane >> 3) & 1) * 8;
    const int b1col = ((lane >> 4) & 1) * 8;

    for (int it = 0; it < nIter; ++it) {
        asm volatile("cp.async.wait_group 1;" ::: "memory");
        __syncthreads();

        const uint32_t aS = sb + (uint32_t)(it % NSTAGE) * STG;
        const uint32_t bS = aS + A_BYT;

#pragma unroll
        for (int kk = 0; kk < 4; kk++) {
            uint32_t a[MI][4];
#pragma unroll
            for (int mi = 0; mi < MI; mi++) {
                uint32_t addr = aS + (uint32_t)((((wm * MI + mi) * 16 + arow) * SA) + kk * 16 + acol) * 2;
                ldsm4(a[mi][0], a[mi][1], a[mi][2], a[mi][3], addr);
            }
            uint32_t b[2][4];
#pragma unroll
            for (int nb = 0; nb < 2; nb++) {
                if (MODEB) {
                    uint32_t addr = bS + (uint32_t)(((kk * 16 + b1row) * SB1) + wn * 32 + nb * 16 + b1col) * 2;
                    ldsm4t(b[nb][0], b[nb][1], b[nb][2], b[nb][3], addr);
                } else {
                    uint32_t addr = bS + (uint32_t)(((wn * 32 + nb * 16 + b0row) * SA) + kk * 16 + b0col) * 2;
                    ldsm4(b[nb][0], b[nb][1], b[nb][2], b[nb][3], addr);
                }
            }
#pragma unroll
            for (int mi = 0; mi < MI; mi++)
#pragma unroll
                for (int nj = 0; nj < 4; nj++)
                    mma16816(acc[mi][nj], a[mi],
                             b[nj >> 1][2 * (nj & 1)], b[nj >> 1][2 * (nj & 1) + 1]);

            if (kk == 0) {
                if (it + 2 < nIter) load((it + 2) % NSTAGE);
                else asm volatile("cp.async.commit_group;" ::: "memory");
            }
        }
    }

#pragma unroll
    for (int mi = 0; mi < MI; mi++) {
        const int r0 = bm + (wm * MI + mi) * 16 + (lane >> 2);
#pragma unroll
        for (int nj = 0; nj < 4; nj++) {
            const int c0 = bn + wn * 32 + nj * 8 + 2 * (lane & 3);
            const float* ac = acc[mi][nj];
            if (r0 < M && c0 < N)
                *(float2*)(Cp + (size_t)r0 * ldC + c0) =
                    make_float2(ac[0] * alpha, ac[1] * alpha);
            if (r0 + 8 < M && c0 < N)
                *(float2*)(Cp + (size_t)(r0 + 8) * ldC + c0) =
                    make_float2(ac[2] * alpha, ac[3] * alpha);
        }
    }
}

// ---------------------------------------------------------------------------
__global__ void reduce2h(const float* __restrict__ P, size_t CH,
                         __half* __restrict__ out, int n4) {
    int i = blockIdx.x * blockDim.x + threadIdx.x;
    if (i < n4) {
        float4 a = *(const float4*)(P + 4 * (size_t)i);
        float4 b = *(const float4*)(P + CH + 4 * (size_t)i);
        __half2* o = (__half2*)(out + 4 * (size_t)i);
        o[0] = __floats2half2_rn(a.x + b.x, a.y + b.y);
        o[1] = __floats2half2_rn(a.z + b.z, a.w + b.w);
    }
}
__global__ void reduce2f(const float* __restrict__ P, size_t CH,
                         float* __restrict__ out, int n4) {
    int i = blockIdx.x * blockDim.x + threadIdx.x;
    if (i < n4) {
        float4 a = *(const float4*)(P + 4 * (size_t)i);
        float4 b = *(const float4*)(P + CH + 4 * (size_t)i);
        *(float4*)(out + 4 * (size_t)i) =
            make_float4(a.x + b.x, a.y + b.y, a.z + b.z, a.w + b.w);
    }
}

// ---------------------------------------------------------------------------
__global__ void cvt1(const float4* __restrict__ s, __half2* __restrict__ d, int n4) {
    int i = blockIdx.x * blockDim.x + threadIdx.x;
    if (i < n4) {
        float4 v = s[i];
        d[2 * i]     = __floats2half2_rn(v.x, v.y);
        d[2 * i + 1] = __floats2half2_rn(v.z, v.w);
    }
}
__global__ void cvt_fuse3(const float4* __restrict__ q, const float4* __restrict__ k,
                          const float4* __restrict__ v, __half* __restrict__ d, int n4) {
    int i = blockIdx.x * blockDim.x + threadIdx.x;
    if (i < n4) {
        int p = i * 4;
        int row = p >> 11, col = p & 2047;
        float4 a;
        __half2* dq = (__half2*)(d + (size_t)row * NQKV + col);
        a = q[i]; dq[0] = __floats2half2_rn(a.x, a.y); dq[1] = __floats2half2_rn(a.z, a.w);
        __half2* dk = (__half2*)(d + (size_t)row * NQKV + 2048 + col);
        a = k[i]; dk[0] = __floats2half2_rn(a.x, a.y); dk[1] = __floats2half2_rn(a.z, a.w);
        __half2* dv = (__half2*)(d + (size_t)row * NQKV + 4096 + col);
        a = v[i]; dv[0] = __floats2half2_rn(a.x, a.y); dv[1] = __floats2half2_rn(a.z, a.w);
    }
}

// ---------------------------------------------------------------------------
#define QR_BLOCKS 25
#define QR_ROWS   20
#define QR_THREADS (NREL * 32)
#define QR_SMEM ((NREL * DM + DM) * 4)

__global__ __launch_bounds__(QR_THREADS, 1) void qr_kernel(
    const __half* __restrict__ Q, int ldQ, const float* __restrict__ wk,
    float* __restrict__ QR, float scale)
{
    extern __shared__ float qsm[];
    float* wks = qsm;
    float* qv  = qsm + NREL * DM;
    const int tid = threadIdx.x, warp = tid / 32, lane = tid & 31;

    for (int t = tid; t < NREL * DM; t += QR_THREADS) wks[t] = wk[t];
    __syncthreads();

    for (int ii = 0; ii < QR_ROWS; ii++) {
        const int i = blockIdx.x * QR_ROWS + ii;
        for (int t = tid; t < DM; t += QR_THREADS)
            qv[t] = __half2float(Q[(size_t)i * ldQ + t]);
        __syncthreads();
        if (warp < NREL) {
            float s = 0.f;
            const float* wp = wks + warp * DM;
#pragma unroll 4
            for (int k = lane; k < DM; k += 32) s += qv[k] * wp[k];
#pragma unroll
            for (int o = 16; o > 0; o >>= 1) s += __shfl_xor_sync(0xffffffffu, s, o);
            if (lane == 0) QR[i * NREL + warp] = s * scale;
        }
        __syncthreads();
    }
}

// ---------------------------------------------------------------------------
__global__ __launch_bounds__(512) void softmax_kernel(
    const float* __restrict__ SP, float* __restrict__ S,
    const float* __restrict__ QR, const int* __restrict__ mask,
    float* __restrict__ Aout, __half* __restrict__ A16, int n)
{
    const int i = blockIdx.x;
    __shared__ float red[512];
    const size_t CH = (size_t)NTOK * NTOK;
    float* row = S + (size_t)i * n;
    const int* mrow = mask + (size_t)i * n;
    float* arow = Aout + (size_t)i * n;
    __half* hrow = A16 + (size_t)i * NTOKP;

    float m = -INFINITY;
    for (int j = threadIdx.x; j < n; j += blockDim.x) {
        float v = 0.f;
        const size_t off = (size_t)i * n + j;
#pragma unroll
        for (int z = 0; z < SPL_S; z++) v += SP[z * CH + off];
        int d = j - i;
        d = min(max(d, -KWIN), KWIN);
        v += QR[i * NREL + d + KWIN];
        if (mrow[j] == 0) v = -1e9f;
        row[j] = v;
        m = fmaxf(m, v);
    }
    red[threadIdx.x] = m;
    __syncthreads();
    for (int s = 256; s > 0; s >>= 1) {
        if (threadIdx.x < s) red[threadIdx.x] = fmaxf(red[threadIdx.x], red[threadIdx.x + s]);
        __syncthreads();
    }
    m = red[0];
    __syncthreads();

    float sum = 0.f;
    for (int j = threadIdx.x; j < n; j += blockDim.x) {
        float e = expf(row[j] - m);
        row[j] = e;
        sum += e;
    }
    red[threadIdx.x] = sum;
    __syncthreads();
    for (int s = 256; s > 0; s >>= 1) {
        if (threadIdx.x < s) red[threadIdx.x] += red[threadIdx.x + s];
        __syncthreads();
    }
    const float inv = 1.0f / red[0];
    __syncthreads();

    for (int j = threadIdx.x; j < n; j += blockDim.x) {
        float a = row[j] * inv;
        arow[j] = a;
        hrow[j] = __float2half_rn(a);
    }
    for (int j = n + threadIdx.x; j < NTOKP; j += blockDim.x) hrow[j] = __float2half_rn(0.f);
}

// ---------------------------------------------------------------------------
extern "C" void kernel_launch(void* const* d_in, const int* in_sizes, int n_in,
                              void* d_out, int out_size)
{
    const float* X    = (const float*)d_in[0];
    const int*   mask = (const int*)  d_in[1];
    const float* Wq   = (const float*)d_in[2];
    const float* Wk   = (const float*)d_in[3];
    const float* Wv   = (const float*)d_in[4];
    const float* Wo   = (const float*)d_in[5];
    const float* wk   = (const float*)d_in[6];

    float* Y    = (float*)d_out;                 // [500, 2048]
    float* Aout = Y + (size_t)NTOK * DM;         // [500, 500]

    __half *X16, *W16, *Wo16, *QKV16, *A16, *T16;
    float *P, *S, *QR;
    cudaGetSymbolAddress((void**)&X16,   g_X16);
    cudaGetSymbolAddress((void**)&W16,   g_W16);
    cudaGetSymbolAddress((void**)&Wo16,  g_Wo16);
    cudaGetSymbolAddress((void**)&QKV16, g_QKV16);
    cudaGetSymbolAddress((void**)&A16,   g_A16);
    cudaGetSymbolAddress((void**)&T16,   g_T16);
    cudaGetSymbolAddress((void**)&P,     g_P);
    cudaGetSymbolAddress((void**)&S,     g_S);
    cudaGetSymbolAddress((void**)&QR,    g_QR);

    const int SM_1_4 = NSTAGE * (128 * SA * 2 + 64 * SB1 * 2);   // 107520
    const int SM_0_2 = NSTAGE * (64 * SA * 2 + 128 * SA * 2);    // 82944
    const int SM_1_2 = NSTAGE * (64 * SA * 2 + 64 * SB1 * 2);    // 79872
    cudaFuncSetAttribute((const void*)hgemm<1,4>, cudaFuncAttributeMaxDynamicSharedMemorySize, SM_1_4);
    cudaFuncSetAttribute((const void*)hgemm<0,2>, cudaFuncAttributeMaxDynamicSharedMemorySize, SM_0_2);
    cudaFuncSetAttribute((const void*)hgemm<1,2>, cudaFuncAttributeMaxDynamicSharedMemorySize, SM_1_2);
    cudaFuncSetAttribute((const void*)qr_kernel,  cudaFuncAttributeMaxDynamicSharedMemorySize, QR_SMEM);

    static cudaStream_t s2 = nullptr;
    static cudaEvent_t e0 = nullptr, eW0 = nullptr, eZ1 = nullptr,
                       eQ = nullptr, eR = nullptr, eWo = nullptr;
    if (!s2) {
        cudaStreamCreateWithFlags(&s2, cudaStreamNonBlocking);
        cudaEventCreateWithFlags(&e0,  cudaEventDisableTiming);
        cudaEventCreateWithFlags(&eW0, cudaEventDisableTiming);
        cudaEventCreateWithFlags(&eZ1, cudaEventDisableTiming);
        cudaEventCreateWithFlags(&eQ,  cudaEventDisableTiming);
        cudaEventCreateWithFlags(&eR,  cudaEventDisableTiming);
        cudaEventCreateWithFlags(&eWo, cudaEventDisableTiming);
    }

    const float scale = 1.0f / sqrtf((float)DM);
    const size_t CH_QKV = (size_t)NTOK * NQKV;
    const size_t CH_S   = (size_t)NTOK * NTOK;
    const size_t CH_TD  = (size_t)NTOK * DM;
    const int HALF4 = DM * DM / 8;          // float4 count of a 1024-row W slab
    const int HOFF4 = 1024 * DM / 4;        // float4 offset of slab 1

    // fork side stream
    cudaEventRecord(e0, 0);
    cudaStreamWaitEvent(s2, e0, 0);

    // main: X cvt, then W slab 0 (k rows 0..1023) at full bandwidth
    cvt1<<<(NTOK * DM / 4 + 255) / 256, 256>>>((const float4*)X, (__half2*)X16, NTOK * DM / 4);
    cvt_fuse3<<<(HALF4 + 255) / 256, 256>>>(
        (const float4*)Wq, (const float4*)Wk, (const float4*)Wv, W16, HALF4);
    cudaEventRecord(eW0, 0);

    // main: QKV split chunk z=0 (k 0..1023) starts immediately
    hgemm<1,4><<<dim3(NQKV / 128, 4, 1), 256, SM_1_4>>>(
        X16, W16, P, NTOK, NQKV, 1024, DM, DM, NQKV, NQKV, CH_QKV, 1.0f, 0);

    // side: W slab 1 cvt (hidden under z=0), then QKV chunk z=1, then Wo cvt
    cudaStreamWaitEvent(s2, eW0, 0);
    cvt_fuse3<<<(HALF4 + 255) / 256, 256, 0, s2>>>(
        (const float4*)Wq + HOFF4, (const float4*)Wk + HOFF4, (const float4*)Wv + HOFF4,
        W16 + (size_t)1024 * NQKV, HALF4);
    hgemm<1,4><<<dim3(NQKV / 128, 4, 1), 256, SM_1_4, s2>>>(
        X16, W16, P, NTOK, NQKV, 1024, DM, DM, NQKV, NQKV, CH_QKV, 1.0f, 1);
    cudaEventRecord(eZ1, s2);
    cvt1<<<(DM * DM / 4 + 255) / 256, 256, 0, s2>>>(
        (const float4*)Wo, (__half2*)Wo16, DM * DM / 4);
    cudaEventRecord(eWo, s2);

    // main: join z=1, reduce partials to fp16 QKV
    cudaStreamWaitEvent(0, eZ1, 0);
    reduce2h<<<((int)CH_QKV / 4 + 255) / 256, 256>>>(P, CH_QKV, QKV16, (int)CH_QKV / 4);
    cudaEventRecord(eQ, 0);

    // side: QR concurrent with S GEMM
    cudaStreamWaitEvent(s2, eQ, 0);
    qr_kernel<<<QR_BLOCKS, QR_THREADS, QR_SMEM, s2>>>(QKV16, NQKV, wk, QR, scale);
    cudaEventRecord(eR, s2);

    // main: S partials = scale * Q @ K^T, split-K 8
    hgemm<0,2><<<dim3(4, 8, SPL_S), 256, SM_0_2>>>(
        QKV16, QKV16 + DM, P, NTOK, NTOK, 256, DM, NQKV, NQKV, NTOK, CH_S, scale, 0);

    // main: fused 8-way reduce + bias + mask + softmax (needs qr)
    cudaStreamWaitEvent(0, eR, 0);
    softmax_kernel<<<NTOK, 512>>>(P, S, QR, mask, Aout, A16, NTOK);

    // main: T = A @ V, split-K 2
    hgemm<1,2><<<dim3(DM / 128, 8, 2), 256, SM_1_2>>>(
        A16, QKV16 + 2 * DM, P, NTOK, DM, 256, NTOK, NTOKP, NQKV, DM, CH_TD, 1.0f, 0);
    reduce2h<<<((int)CH_TD / 4 + 255) / 256, 256>>>(P, CH_TD, T16, (int)CH_TD / 4);

    // main: Y = T @ Wo, split-K 2 (needs Wo16)
    cudaStreamWaitEvent(0, eWo, 0);
    hgemm<1,2><<<dim3(DM / 128, 8, 2), 256, SM_1_2>>>(
        T16, Wo16, P, NTOK, DM, 1024, DM, DM, DM, DM, CH_TD, 1.0f, 0);
    reduce2f<<<((int)CH_TD / 4 + 255) / 256, 256>>>(P, CH_TD, Y, (int)CH_TD / 4);
}